// round 3
// baseline (speedup 1.0000x reference)
#include <cuda_runtime.h>
#include <math.h>

#define BB 8
#define MM 2048
#define FF 128

__device__ float  g_h[BB*MM*FF];   // h = x @ W  (8.4 MB)
__device__ float4 g_rp[BB*MM];     // per-row (e^{s1}, e^{.2 s1}, e^{s2}, e^{.2 s2})

// ---------------------------------------------------------------------------
// K1: h = x@W, fused row stats. grid (64, 8), block 256. CTA = 32 rows.
// row = tid>>3, cg = tid&7; thread owns cols {cg*4 + 32t + j}.
// ---------------------------------------------------------------------------
__global__ __launch_bounds__(256) void k_hgemm(const float* __restrict__ x,
                                               const float* __restrict__ W,
                                               const float* __restrict__ a)
{
    __shared__ float Ws[64][128];
    __shared__ float xs[32][68];

    const int b   = blockIdx.y;
    const int m0  = blockIdx.x * 32;
    const int tid = threadIdx.x;
    const int row = tid >> 3;
    const int cg  = tid & 7;

    float acc[16];
#pragma unroll
    for (int j = 0; j < 16; j++) acc[j] = 0.f;

    const float* xb = x + ((size_t)b*MM + m0) * FF;

    for (int ch = 0; ch < 2; ch++) {
        const float4* Wv  = (const float4*)(W + ch*64*FF);
        float4*       Wsv = (float4*)(&Ws[0][0]);
#pragma unroll
        for (int i = 0; i < 8; i++) Wsv[tid + i*256] = Wv[tid + i*256];
#pragma unroll
        for (int i = 0; i < 2; i++) {
            int idx = tid + i*256;
            int r = idx >> 4, q = (idx & 15) * 4;
            float4 v = *(const float4*)(xb + (size_t)r*FF + ch*64 + q);
            xs[r][q] = v.x; xs[r][q+1] = v.y; xs[r][q+2] = v.z; xs[r][q+3] = v.w;
        }
        __syncthreads();
#pragma unroll 8
        for (int i = 0; i < 64; i++) {
            float xv = xs[row][i];
#pragma unroll
            for (int t = 0; t < 4; t++)
#pragma unroll
                for (int j = 0; j < 4; j++)
                    acc[t*4+j] = fmaf(xv, Ws[i][cg*4 + t*32 + j], acc[t*4+j]);
        }
        __syncthreads();
    }

    float* hrow = g_h + ((size_t)b*MM + m0 + row) * FF;
#pragma unroll
    for (int t = 0; t < 4; t++)
        *(float4*)(hrow + cg*4 + t*32) =
            make_float4(acc[t*4], acc[t*4+1], acc[t*4+2], acc[t*4+3]);

    float p1 = 0.f, p2 = 0.f;
#pragma unroll
    for (int t = 0; t < 4; t++)
#pragma unroll
        for (int j = 0; j < 4; j++) {
            int col = cg*4 + t*32 + j;
            p1 = fmaf(acc[t*4+j], a[col],      p1);
            p2 = fmaf(acc[t*4+j], a[128+col],  p2);
        }
#pragma unroll
    for (int o = 4; o > 0; o >>= 1) {
        p1 += __shfl_down_sync(0xffffffffu, p1, o, 8);
        p2 += __shfl_down_sync(0xffffffffu, p2, o, 8);
    }
    if (cg == 0)
        g_rp[(size_t)b*MM + m0 + row] =
            make_float4(expf(p1), expf(0.2f*p1), expf(p2), expf(0.2f*p2));
}

// ---------------------------------------------------------------------------
// K2: fused attention. grid (32, 8), block 256. CTA = 64 rows, n tiles of 32.
// Phase A: nn = tid&31, rows rbase=(tid>>5)*8 .. +7  (build w + den)
// Phase C: km = tid&15 (k0=km*8), mg = tid>>4, rows {mg+16i}
// ---------------------------------------------------------------------------
__global__ __launch_bounds__(256) void k_attn(const int* __restrict__ adj,
                                              float* __restrict__ out)
{
    __shared__ float hs[32][128];
    __shared__ float ws[64][33];
    __shared__ float den_s[64];

    const int b   = blockIdx.y;
    const int m0  = blockIdx.x * 64;
    const int tid = threadIdx.x;

    const int nn    = tid & 31;
    const int rbase = (tid >> 5) * 8;
    const int km = tid & 15;
    const int mg = tid >> 4;
    const int k0 = km * 8;

    float c1r[8], c2r[8], denp[8];
#pragma unroll
    for (int i = 0; i < 8; i++) {
        float4 rp = g_rp[(size_t)b*MM + m0 + rbase + i];
        c1r[i] = rp.x; c2r[i] = rp.y; denp[i] = 0.f;
    }

    float acc[4][8];
#pragma unroll
    for (int i = 0; i < 4; i++)
#pragma unroll
        for (int j = 0; j < 8; j++) acc[i][j] = 0.f;

    const int*    adjbase = adj + ((size_t)b*MM + m0 + rbase) * MM + nn;
    const float4* hv      = (const float4*)(g_h + (size_t)b*MM*FF);
    const float4* rpn     = (const float4*)(g_rp + (size_t)b*MM);

    for (int n0 = 0; n0 < MM; n0 += 32) {
        __syncthreads();
        // Phase A
        float4 rp = rpn[n0 + nn];
        const int* ap = adjbase + n0;
#pragma unroll
        for (int i = 0; i < 8; i++) {
            int av = ap[(size_t)i * MM];
            float w = av ? fmaxf(c1r[i]*rp.z, c2r[i]*rp.w) : 0.f;
            ws[rbase + i][nn] = w;
            denp[i] += w;
        }
        // Phase B
        {
            const float4* hsrc = hv + (size_t)n0 * (FF/4);
            float4*       hdst = (float4*)(&hs[0][0]);
#pragma unroll
            for (int i = 0; i < 4; i++) hdst[tid + i*256] = hsrc[tid + i*256];
        }
        __syncthreads();
        // Phase C
#pragma unroll 2
        for (int n = 0; n < 32; n++) {
            float4 ha = *(const float4*)(&hs[n][k0]);
            float4 hb = *(const float4*)(&hs[n][k0+4]);
#pragma unroll
            for (int i = 0; i < 4; i++) {
                float w = ws[mg + 16*i][n];
                acc[i][0] = fmaf(w, ha.x, acc[i][0]);
                acc[i][1] = fmaf(w, ha.y, acc[i][1]);
                acc[i][2] = fmaf(w, ha.z, acc[i][2]);
                acc[i][3] = fmaf(w, ha.w, acc[i][3]);
                acc[i][4] = fmaf(w, hb.x, acc[i][4]);
                acc[i][5] = fmaf(w, hb.y, acc[i][5]);
                acc[i][6] = fmaf(w, hb.z, acc[i][6]);
                acc[i][7] = fmaf(w, hb.w, acc[i][7]);
            }
        }
    }

    // den: reduce over 32 lanes (each warp owns rows rbase..rbase+7)
#pragma unroll
    for (int i = 0; i < 8; i++)
#pragma unroll
        for (int o = 16; o > 0; o >>= 1)
            denp[i] += __shfl_down_sync(0xffffffffu, denp[i], o);
    if (nn == 0) {
#pragma unroll
        for (int i = 0; i < 8; i++) den_s[rbase + i] = denp[i];
    }
    __syncthreads();

    // epilogue: normalize + ELU + store
    float* ob = out + ((size_t)b*MM + m0) * FF;
#pragma unroll
    for (int i = 0; i < 4; i++) {
        int m = mg + 16*i;
        float inv = 1.0f / den_s[m];
        float v[8];
#pragma unroll
        for (int j = 0; j < 8; j++) {
            float t = acc[i][j] * inv;
            v[j] = (t > 0.f) ? t : expm1f(t);
        }
        *(float4*)(ob + (size_t)m*FF + k0)     = make_float4(v[0], v[1], v[2], v[3]);
        *(float4*)(ob + (size_t)m*FF + k0 + 4) = make_float4(v[4], v[5], v[6], v[7]);
    }
}

extern "C" void kernel_launch(void* const* d_in, const int* in_sizes, int n_in,
                              void* d_out, int out_size)
{
    const float* x   = (const float*)d_in[0];
    const int*   adj = (const int*)d_in[1];
    const float* W   = (const float*)d_in[2];
    const float* a   = (const float*)d_in[3];
    float*       out = (float*)d_out;

    k_hgemm<<<dim3(MM/32, BB), 256>>>(x, W, a);
    k_attn<<<dim3(MM/64, BB), 256>>>(adj, out);
}

// round 4
// speedup vs baseline: 1.4021x; 1.4021x over previous
#include <cuda_runtime.h>
#include <math.h>

#define BB 8
#define MM 2048
#define FF 128
#define NT 32               // n per tile
#define MT 128              // m rows per attn CTA
#define NSPLIT 2
#define NHALF (MM/NSPLIT)   // 1024
#define NITER (NHALF/NT)    // 32

__device__ float  g_h[BB*MM*FF];            // h = x @ W (8.4 MB)
__device__ float4 g_rp[BB*MM];              // (e^{s1}, e^{.2s1}, e^{s2}, e^{.2s2})
__device__ float  g_num[NSPLIT][BB*MM*FF];  // partial numerators (16.8 MB)
__device__ float  g_den[NSPLIT][BB*MM];     // partial denominators

#define FFMA2(acc, a, b) asm("fma.rn.f32x2 %0, %1, %2, %0;" : "+l"(acc) : "l"(a), "l"(b))

__device__ __forceinline__ void cp_async16(unsigned dst, const void* src) {
    asm volatile("cp.async.cg.shared.global [%0], [%1], 16;" :: "r"(dst), "l"(src));
}

// ---------------------------------------------------------------------------
// K1: h = x@W, fused row stats. grid (64, 8), block 256. CTA = 32 rows.
// ---------------------------------------------------------------------------
__global__ __launch_bounds__(256) void k_hgemm(const float* __restrict__ x,
                                               const float* __restrict__ W,
                                               const float* __restrict__ a)
{
    __shared__ float Ws[64][128];
    __shared__ float xs[32][68];

    const int b   = blockIdx.y;
    const int m0  = blockIdx.x * 32;
    const int tid = threadIdx.x;
    const int row = tid >> 3;
    const int cg  = tid & 7;

    float acc[16];
#pragma unroll
    for (int j = 0; j < 16; j++) acc[j] = 0.f;

    const float* xb = x + ((size_t)b*MM + m0) * FF;

    for (int ch = 0; ch < 2; ch++) {
        const float4* Wv  = (const float4*)(W + ch*64*FF);
        float4*       Wsv = (float4*)(&Ws[0][0]);
#pragma unroll
        for (int i = 0; i < 8; i++) Wsv[tid + i*256] = Wv[tid + i*256];
#pragma unroll
        for (int i = 0; i < 2; i++) {
            int idx = tid + i*256;
            int r = idx >> 4, q = (idx & 15) * 4;
            float4 v = *(const float4*)(xb + (size_t)r*FF + ch*64 + q);
            xs[r][q] = v.x; xs[r][q+1] = v.y; xs[r][q+2] = v.z; xs[r][q+3] = v.w;
        }
        __syncthreads();
#pragma unroll 8
        for (int i = 0; i < 64; i++) {
            float xv = xs[row][i];
#pragma unroll
            for (int t = 0; t < 4; t++)
#pragma unroll
                for (int j = 0; j < 4; j++)
                    acc[t*4+j] = fmaf(xv, Ws[i][cg*4 + t*32 + j], acc[t*4+j]);
        }
        __syncthreads();
    }

    float* hrow = g_h + ((size_t)b*MM + m0 + row) * FF;
#pragma unroll
    for (int t = 0; t < 4; t++)
        *(float4*)(hrow + cg*4 + t*32) =
            make_float4(acc[t*4], acc[t*4+1], acc[t*4+2], acc[t*4+3]);

    float p1 = 0.f, p2 = 0.f;
#pragma unroll
    for (int t = 0; t < 4; t++)
#pragma unroll
        for (int j = 0; j < 4; j++) {
            int col = cg*4 + t*32 + j;
            p1 = fmaf(acc[t*4+j], a[col],      p1);
            p2 = fmaf(acc[t*4+j], a[128+col],  p2);
        }
#pragma unroll
    for (int o = 4; o > 0; o >>= 1) {
        p1 += __shfl_down_sync(0xffffffffu, p1, o, 8);
        p2 += __shfl_down_sync(0xffffffffu, p2, o, 8);
    }
    if (cg == 0)
        g_rp[(size_t)b*MM + m0 + row] =
            make_float4(expf(p1), expf(0.2f*p1), expf(p2), expf(0.2f*p2));
}

// ---------------------------------------------------------------------------
// K2: fused masked attention (partial over one n-half).
// grid (MM/MT=16, BB=8, NSPLIT=2), block 256, dyn smem 67584.
// Phase A: c = tid&7 (n-quad), r2 = tid>>3 -> rows {r2+32i}
// Phase C: kg = tid&15 (k-pairs p=kg+16q), mg = tid>>4 -> rows {mg+16i}
// ---------------------------------------------------------------------------
__global__ __launch_bounds__(256, 2) void k_attn(const int* __restrict__ adj)
{
    extern __shared__ char sm_raw[];
    // hs2: [2][NT][64] ull (h tile, p = k>>1 natural order)     32768 B
    // ws2: [128][33] float2 (w duplicated, padded)              33792 B
    // c12: [128] float2 (per-row e^{s1}, e^{.2 s1})              1024 B
    unsigned long long* hs2 = (unsigned long long*)sm_raw;
    float2* ws2 = (float2*)(sm_raw + 32768);
    float2* c12 = (float2*)(sm_raw + 32768 + 33792);
#define WS2(r,n) ws2[(r)*33 + (n)]

    const int b    = blockIdx.y;
    const int m0   = blockIdx.x * MT;
    const int half = blockIdx.z;
    const int tid  = threadIdx.x;
    const int nbase = half * NHALF;

    if (tid < 128) {
        float4 rp = g_rp[(size_t)b*MM + m0 + tid];
        c12[tid] = make_float2(rp.x, rp.y);
    }

    const int c  = tid & 7;
    const int r2 = tid >> 3;
    const int kg = tid & 15;
    const int mg = tid >> 4;

    float denp[4] = {0.f, 0.f, 0.f, 0.f};
    unsigned long long acc[8][4];
#pragma unroll
    for (int i = 0; i < 8; i++)
#pragma unroll
        for (int q = 0; q < 4; q++) acc[i][q] = 0ull;

    const int* adjp = adj + ((size_t)(b*MM + m0 + r2)) * MM + nbase + c*4;
    const float4* rpb = &g_rp[(size_t)b*MM + nbase];

    // prologue: adj tile 0 into regs, h tile 0 via cp.async into buf 0
    int4 adjv[4];
#pragma unroll
    for (int i = 0; i < 4; i++)
        adjv[i] = __ldg((const int4*)(adjp + (size_t)32*i*MM));
    {
        const float4* src = (const float4*)(g_h + ((size_t)b*MM + nbase)*FF);
        unsigned dstb = (unsigned)__cvta_generic_to_shared(hs2);
#pragma unroll
        for (int e = 0; e < 4; e++)
            cp_async16(dstb + (tid + 256*e)*16, src + tid + 256*e);
        asm volatile("cp.async.commit_group;");
    }
    __syncthreads();   // c12 visible

    for (int t = 0; t < NITER; t++) {
        const int buf = t & 1;

        // ---- Phase A: w tile (duplicated float2) + den ----
        float2 cc[4];
#pragma unroll
        for (int i = 0; i < 4; i++) cc[i] = c12[r2 + 32*i];
        const float4* rpn = rpb + t*NT;
#pragma unroll
        for (int j = 0; j < 4; j++) {
            float4 rv = __ldg(rpn + c*4 + j);
            const int nl = c*4 + j;
#pragma unroll
            for (int i = 0; i < 4; i++) {
                int av = (&adjv[i].x)[j];
                float w = av ? fmaxf(cc[i].x*rv.z, cc[i].y*rv.w) : 0.f;
                WS2(r2 + 32*i, nl) = make_float2(w, w);
                denp[i] += w;
            }
        }

        // prefetch adj for next tile
        {
            const int tn = (t+1 < NITER) ? (t+1)*NT : 0;
#pragma unroll
            for (int i = 0; i < 4; i++)
                adjv[i] = __ldg((const int4*)(adjp + (size_t)32*i*MM + tn));
        }

        asm volatile("cp.async.wait_group 0;");
        __syncthreads();   // hs2[buf] + ws2 ready

        // issue cp.async for next h tile into buf^1
        if (t+1 < NITER) {
            const float4* src = (const float4*)(g_h + ((size_t)b*MM + nbase + (t+1)*NT)*FF);
            unsigned dstb = (unsigned)__cvta_generic_to_shared(hs2 + (buf^1)*NT*64);
#pragma unroll
            for (int e = 0; e < 4; e++)
                cp_async16(dstb + (tid + 256*e)*16, src + tid + 256*e);
        }
        asm volatile("cp.async.commit_group;");

        // ---- Phase C: acc += w * h  (packed f32x2) ----
        const unsigned long long* hb = hs2 + buf*NT*64;
#pragma unroll 2
        for (int n = 0; n < NT; n++) {
            unsigned long long h0 = hb[n*64 + kg];
            unsigned long long h1 = hb[n*64 + kg + 16];
            unsigned long long h2 = hb[n*64 + kg + 32];
            unsigned long long h3 = hb[n*64 + kg + 48];
#pragma unroll
            for (int i = 0; i < 8; i++) {
                unsigned long long w = *(const unsigned long long*)&WS2(mg + 16*i, n);
                FFMA2(acc[i][0], w, h0);
                FFMA2(acc[i][1], w, h1);
                FFMA2(acc[i][2], w, h2);
                FFMA2(acc[i][3], w, h3);
            }
        }
        __syncthreads();   // ws2 consumed before next phase A
    }

    // den: reduce over the 8 c-lanes (same warp), write partials
#pragma unroll
    for (int i = 0; i < 4; i++)
#pragma unroll
        for (int o = 4; o > 0; o >>= 1)
            denp[i] += __shfl_down_sync(0xffffffffu, denp[i], o, 8);
    if (c == 0) {
#pragma unroll
        for (int i = 0; i < 4; i++)
            g_den[half][(size_t)b*MM + m0 + r2 + 32*i] = denp[i];
    }

    // num partials: thread owns rows {mg+16i}, k pairs {2kg+32q, +1}
    float* nb = g_num[half] + ((size_t)b*MM + m0) * FF;
#pragma unroll
    for (int i = 0; i < 8; i++)
#pragma unroll
        for (int q = 0; q < 4; q++)
            *(unsigned long long*)(nb + (size_t)(mg + 16*i)*FF + 2*kg + 32*q) = acc[i][q];
}

// ---------------------------------------------------------------------------
// K3: combine halves, normalize, ELU. grid 2048, block 256.
// ---------------------------------------------------------------------------
__global__ __launch_bounds__(256) void k_comb(float* __restrict__ out)
{
    const int idx = blockIdx.x*256 + threadIdx.x;   // float4 index
    const int row = idx >> 5;
    float4 a = ((const float4*)g_num[0])[idx];
    float4 b4 = ((const float4*)g_num[1])[idx];
    float inv = 1.0f / (g_den[0][row] + g_den[1][row]);
    float v0 = (a.x + b4.x) * inv;
    float v1 = (a.y + b4.y) * inv;
    float v2 = (a.z + b4.z) * inv;
    float v3 = (a.w + b4.w) * inv;
    v0 = v0 > 0.f ? v0 : expm1f(v0);
    v1 = v1 > 0.f ? v1 : expm1f(v1);
    v2 = v2 > 0.f ? v2 : expm1f(v2);
    v3 = v3 > 0.f ? v3 : expm1f(v3);
    ((float4*)out)[idx] = make_float4(v0, v1, v2, v3);
}

extern "C" void kernel_launch(void* const* d_in, const int* in_sizes, int n_in,
                              void* d_out, int out_size)
{
    const float* x   = (const float*)d_in[0];
    const int*   adj = (const int*)d_in[1];
    const float* W   = (const float*)d_in[2];
    const float* a   = (const float*)d_in[3];
    float*       out = (float*)d_out;

    static int smem_set = 0;
    if (!smem_set) {
        cudaFuncSetAttribute(k_attn, cudaFuncAttributeMaxDynamicSharedMemorySize, 67584);
        smem_set = 1;
    }

    k_hgemm<<<dim3(MM/32, BB), 256>>>(x, W, a);
    k_attn<<<dim3(MM/MT, BB, NSPLIT), 256, 67584>>>(adj);
    k_comb<<<dim3(BB*MM*FF/4/256), 256>>>(out);
}

// round 6
// speedup vs baseline: 2.4323x; 1.7347x over previous
#include <cuda_runtime.h>
#include <cuda_bf16.h>
#include <math.h>
#include <stdint.h>

#define BB 8
#define MM 2048
#define FF 128
#define NT 32
#define NITER (MM/NT)   // 64
#define MT 128

// ---- scratch ----
__device__ __nv_bfloat16 g_ht_hi[BB*FF*MM];  // h^T hi  [b][f][n]  (4.2 MB)
__device__ __nv_bfloat16 g_ht_lo[BB*FF*MM];  // h^T lo
__device__ float2 g_rpA[BB*MM];              // (e^{s1}, e^{0.2 s1})
__device__ float2 g_rpB[BB*MM];              // (e^{s2}, e^{0.2 s2})

__device__ __forceinline__ void cp_async16(uint32_t dst, const void* src) {
    asm volatile("cp.async.cg.shared.global [%0], [%1], 16;" :: "r"(dst), "l"(src));
}

#define LDSM4(r, addr) \
    asm volatile("ldmatrix.sync.aligned.m8n8.x4.shared.b16 {%0,%1,%2,%3}, [%4];" \
        : "=r"((r)[0]), "=r"((r)[1]), "=r"((r)[2]), "=r"((r)[3]) : "r"(addr))

#define MMA16816(c, a, b0, b1) \
    asm volatile("mma.sync.aligned.m16n8k16.row.col.f32.bf16.bf16.f32 " \
        "{%0,%1,%2,%3}, {%4,%5,%6,%7}, {%8,%9}, {%0,%1,%2,%3};" \
        : "+f"((c)[0]), "+f"((c)[1]), "+f"((c)[2]), "+f"((c)[3]) \
        : "r"((a)[0]), "r"((a)[1]), "r"((a)[2]), "r"((a)[3]), "r"(b0), "r"(b1))

__device__ __forceinline__ uint32_t pack_bf16x2(float hi, float lo) {
    uint32_t u;
    asm("cvt.rn.bf16x2.f32 %0, %1, %2;" : "=r"(u) : "f"(hi), "f"(lo));
    return u;
}

// SMEM layout (dynamic):
//  [0, 40960)      w tiles: buf*20480 + comp*10240; 128 rows x 80B (32 bf16 + pad)
//  [40960, 81920)  h tiles: same shape; rows = f
//  [81920, 82432)  den_s (128 f32)
//  [82432, 83456)  c12 (128 float2)
#define SM_W    0
#define SM_H    40960
#define SM_DEN  81920
#define SM_C12  82432
#define SM_TOT  83456
#define COMP_OFF 10240
#define BUF_OFF  20480

// ---------------------------------------------------------------------------
// K1: h = x@W; writes h^T (bf16 hi/lo) + per-row exp coefficients.
// grid (64, 8), block 256. CTA = 32 rows.
// ---------------------------------------------------------------------------
__global__ __launch_bounds__(256) void k_hgemm(const float* __restrict__ x,
                                               const float* __restrict__ W,
                                               const float* __restrict__ a)
{
    __shared__ float Ws[8192];      // [64][128] GEMM stage; reused [32][130] for transpose
    __shared__ float xs[32][68];

    const int b   = blockIdx.y;
    const int m0  = blockIdx.x * 32;
    const int tid = threadIdx.x;
    const int row = tid >> 3;
    const int cg  = tid & 7;

    float acc[16];
#pragma unroll
    for (int j = 0; j < 16; j++) acc[j] = 0.f;

    const float* xb = x + ((size_t)b*MM + m0) * FF;

    for (int ch = 0; ch < 2; ch++) {
        const float4* Wv  = (const float4*)(W + ch*64*FF);
        float4*       Wsv = (float4*)Ws;
#pragma unroll
        for (int i = 0; i < 8; i++) Wsv[tid + i*256] = Wv[tid + i*256];
#pragma unroll
        for (int i = 0; i < 2; i++) {
            int idx = tid + i*256;
            int r = idx >> 4, q = (idx & 15) * 4;
            float4 v = *(const float4*)(xb + (size_t)r*FF + ch*64 + q);
            xs[r][q] = v.x; xs[r][q+1] = v.y; xs[r][q+2] = v.z; xs[r][q+3] = v.w;
        }
        __syncthreads();
#pragma unroll 8
        for (int i = 0; i < 64; i++) {
            float xv = xs[row][i];
#pragma unroll
            for (int t = 0; t < 4; t++)
#pragma unroll
                for (int j = 0; j < 4; j++)
                    acc[t*4+j] = fmaf(xv, Ws[i*128 + cg*4 + t*32 + j], acc[t*4+j]);
        }
        __syncthreads();
    }

    // row stats
    float p1 = 0.f, p2 = 0.f;
#pragma unroll
    for (int t = 0; t < 4; t++)
#pragma unroll
        for (int j = 0; j < 4; j++) {
            int col = cg*4 + t*32 + j;
            p1 = fmaf(acc[t*4+j], a[col],      p1);
            p2 = fmaf(acc[t*4+j], a[128+col],  p2);
        }
#pragma unroll
    for (int o = 4; o > 0; o >>= 1) {
        p1 += __shfl_down_sync(0xffffffffu, p1, o, 8);
        p2 += __shfl_down_sync(0xffffffffu, p2, o, 8);
    }
    if (cg == 0) {
        g_rpA[(size_t)b*MM + m0 + row] = make_float2(expf(p1), expf(0.2f*p1));
        g_rpB[(size_t)b*MM + m0 + row] = make_float2(expf(p2), expf(0.2f*p2));
    }

    // stage acc -> smem [m][f] (stride 130), then transposed bf16 hi/lo writes
#pragma unroll
    for (int t = 0; t < 4; t++)
#pragma unroll
        for (int j = 0; j < 4; j++)
            Ws[row*130 + cg*4 + t*32 + j] = acc[t*4+j];
    __syncthreads();

    const int q  = tid & 7;
    const int fr = tid >> 3;
#pragma unroll
    for (int pass = 0; pass < 4; pass++) {
        int f = fr + 32*pass;
        float v0 = Ws[(q*4+0)*130 + f];
        float v1 = Ws[(q*4+1)*130 + f];
        float v2 = Ws[(q*4+2)*130 + f];
        float v3 = Ws[(q*4+3)*130 + f];
        __nv_bfloat16 h0 = __float2bfloat16_rn(v0);
        __nv_bfloat16 h1 = __float2bfloat16_rn(v1);
        __nv_bfloat16 h2 = __float2bfloat16_rn(v2);
        __nv_bfloat16 h3 = __float2bfloat16_rn(v3);
        uint32_t uh0 = (uint32_t)__bfloat16_as_ushort(h0) | ((uint32_t)__bfloat16_as_ushort(h1) << 16);
        uint32_t uh1 = (uint32_t)__bfloat16_as_ushort(h2) | ((uint32_t)__bfloat16_as_ushort(h3) << 16);
        uint32_t ul0 = pack_bf16x2(v1 - __bfloat162float(h1), v0 - __bfloat162float(h0));
        uint32_t ul1 = pack_bf16x2(v3 - __bfloat162float(h3), v2 - __bfloat162float(h2));
        size_t off = ((size_t)b*FF + f)*MM + m0 + q*4;
        *(uint2*)((char*)g_ht_hi + off*2) = make_uint2(uh0, uh1);
        *(uint2*)((char*)g_ht_lo + off*2) = make_uint2(ul0, ul1);
    }
}

// ---------------------------------------------------------------------------
// stage one h tile (hi+lo) via cp.async: 128 f rows x 64B, into [f][n] rows.
// ---------------------------------------------------------------------------
__device__ __forceinline__ void stage_h(uint32_t hbase, int b, int n0, int tid)
{
#pragma unroll
    for (int e = 0; e < 4; e++) {
        int id    = tid + 256*e;
        int comp  = id >> 9;
        int f     = (id >> 2) & 127;
        int chunk = id & 3;
        const char* base = comp ? (const char*)g_ht_lo : (const char*)g_ht_hi;
        const char* src  = base + (((size_t)b*FF + f)*MM + n0 + chunk*8) * 2;
        cp_async16(hbase + comp*COMP_OFF + f*80 + chunk*16, src);
    }
    asm volatile("cp.async.commit_group;");
}

// ---------------------------------------------------------------------------
// K2: fused masked attention via mma.sync bf16 (3-term compensated).
// grid (16, 8), block 256 (8 warps). CTA = 128 m-rows, full n sweep.
// ---------------------------------------------------------------------------
__global__ __launch_bounds__(256) void k_attn(const int* __restrict__ adj,
                                              float* __restrict__ out)
{
    extern __shared__ char sm[];
    const uint32_t sbase = (uint32_t)__cvta_generic_to_shared(sm);
    float*  den_s = (float*)(sm + SM_DEN);
    float2* c12   = (float2*)(sm + SM_C12);

    const int b    = blockIdx.y;
    const int m0   = blockIdx.x * MT;
    const int tid  = threadIdx.x;
    const int wid  = tid >> 5;
    const int lane = tid & 31;
    const int c    = tid & 7;     // phase-A n quad
    const int r2   = tid >> 3;    // phase-A row base

    if (tid < 128) c12[tid] = g_rpA[(size_t)b*MM + m0 + tid];

    const int* adjp = adj + ((size_t)(b*MM + m0 + r2))*MM + c*4;
    int4 adjv[4];
#pragma unroll
    for (int i = 0; i < 4; i++)
        adjv[i] = __ldg((const int4*)(adjp + (size_t)32*i*MM));

    stage_h(sbase + SM_H, b, 0, tid);
    __syncthreads();

    float2 cc[4];
#pragma unroll
    for (int i = 0; i < 4; i++) cc[i] = c12[r2 + 32*i];
    float denp[4] = {0.f, 0.f, 0.f, 0.f};

    // ldmatrix lane-offset precompute (stride-80 rows; conflict-free pattern)
    const int wrow = wid * 16;
    const uint32_t offA = (uint32_t)((wrow + (lane & 7) + ((lane >> 3) & 1)*8)*80
                                     + (lane >> 4)*16);
    const uint32_t offB = (uint32_t)(((lane & 7) + ((lane >= 16) ? 8 : 0))*80
                                     + ((lane >> 3) & 1)*16);

    float C[16][4];
#pragma unroll
    for (int ft = 0; ft < 16; ft++)
#pragma unroll
        for (int j = 0; j < 4; j++) C[ft][j] = 0.f;

    for (int t = 0; t < NITER; t++) {
        const int buf = t & 1;
        const uint32_t wbase = sbase + SM_W + buf*BUF_OFF;
        const uint32_t hbase = sbase + SM_H + buf*BUF_OFF;

        // ---- build w tile (bf16 hi/lo) + exact fp32 den ----
        {
            const float4* rb = (const float4*)(g_rpB + (size_t)b*MM + t*NT) + c*2;
            float4 v0 = __ldg(rb), v1 = __ldg(rb + 1);
#pragma unroll
            for (int i = 0; i < 4; i++) {
                int4 av = adjv[i];
                int row = r2 + 32*i;
                float w0 = av.x ? fmaxf(cc[i].x*v0.x, cc[i].y*v0.y) : 0.f;
                float w1 = av.y ? fmaxf(cc[i].x*v0.z, cc[i].y*v0.w) : 0.f;
                float w2 = av.z ? fmaxf(cc[i].x*v1.x, cc[i].y*v1.y) : 0.f;
                float w3 = av.w ? fmaxf(cc[i].x*v1.z, cc[i].y*v1.w) : 0.f;
                denp[i] += (w0 + w1) + (w2 + w3);
                __nv_bfloat16 h0 = __float2bfloat16_rn(w0);
                __nv_bfloat16 h1 = __float2bfloat16_rn(w1);
                __nv_bfloat16 h2 = __float2bfloat16_rn(w2);
                __nv_bfloat16 h3 = __float2bfloat16_rn(w3);
                uint32_t uh0 = (uint32_t)__bfloat16_as_ushort(h0) | ((uint32_t)__bfloat16_as_ushort(h1) << 16);
                uint32_t uh1 = (uint32_t)__bfloat16_as_ushort(h2) | ((uint32_t)__bfloat16_as_ushort(h3) << 16);
                uint32_t ul0 = pack_bf16x2(w1 - __bfloat162float(h1), w0 - __bfloat162float(h0));
                uint32_t ul1 = pack_bf16x2(w3 - __bfloat162float(h3), w2 - __bfloat162float(h2));
                uint32_t o = wbase + row*80 + c*8;
                asm volatile("st.shared.v2.b32 [%0], {%1,%2};" :: "r"(o), "r"(uh0), "r"(uh1));
                asm volatile("st.shared.v2.b32 [%0], {%1,%2};" :: "r"(o + COMP_OFF), "r"(ul0), "r"(ul1));
            }
        }

        // adj prefetch for next tile
        {
            const int tn = (t+1 < NITER) ? (t+1)*NT : 0;
#pragma unroll
            for (int i = 0; i < 4; i++)
                adjv[i] = __ldg((const int4*)(adjp + (size_t)32*i*MM + tn));
        }

        asm volatile("cp.async.wait_group 0;");
        __syncthreads();

        if (t+1 < NITER)
            stage_h(sbase + SM_H + (buf^1)*BUF_OFF, b, (t+1)*NT, tid);

        // ---- mma: 2 k16-steps x 16 f-tiles x 3 passes ----
#pragma unroll
        for (int ks = 0; ks < 2; ks++) {
            uint32_t Ah[4], Al[4];
            LDSM4(Ah, wbase + offA + ks*32);
            LDSM4(Al, wbase + offA + ks*32 + COMP_OFF);
#pragma unroll
            for (int fp = 0; fp < 8; fp++) {
                uint32_t baddr = hbase + offB + fp*(16*80) + ks*32;
                uint32_t Bh[4], Bl[4];
                LDSM4(Bh, baddr);
                LDSM4(Bl, baddr + COMP_OFF);
                MMA16816(C[2*fp],   Ah, Bh[0], Bh[1]);
                MMA16816(C[2*fp],   Ah, Bl[0], Bl[1]);
                MMA16816(C[2*fp],   Al, Bh[0], Bh[1]);
                MMA16816(C[2*fp+1], Ah, Bh[2], Bh[3]);
                MMA16816(C[2*fp+1], Ah, Bl[2], Bl[3]);
                MMA16816(C[2*fp+1], Al, Bh[2], Bh[3]);
            }
        }
    }

    // den reduce over the 8 c-lanes sharing each row
#pragma unroll
    for (int i = 0; i < 4; i++)
#pragma unroll
        for (int o = 4; o > 0; o >>= 1)
            denp[i] += __shfl_down_sync(0xffffffffu, denp[i], o, 8);
    if (c == 0) {
#pragma unroll
        for (int i = 0; i < 4; i++) den_s[r2 + 32*i] = denp[i];
    }
    __syncthreads();

    // epilogue: normalize + ELU + store from fragments
    const int R0 = wid*16 + (lane >> 2);
    const float inv0 = 1.0f / den_s[R0];
    const float inv1 = 1.0f / den_s[R0 + 8];
    float* ob = out + ((size_t)b*MM + m0) * FF;
#pragma unroll
    for (int ft = 0; ft < 16; ft++) {
        int f0 = ft*8 + 2*(lane & 3);
        float e0 = C[ft][0] * inv0;
        float e1 = C[ft][1] * inv0;
        float e2 = C[ft][2] * inv1;
        float e3 = C[ft][3] * inv1;
        e0 = e0 > 0.f ? e0 : expm1f(e0);
        e1 = e1 > 0.f ? e1 : expm1f(e1);
        e2 = e2 > 0.f ? e2 : expm1f(e2);
        e3 = e3 > 0.f ? e3 : expm1f(e3);
        *(float2*)(ob + (size_t)R0*FF + f0)     = make_float2(e0, e1);
        *(float2*)(ob + (size_t)(R0+8)*FF + f0) = make_float2(e2, e3);
    }
}

extern "C" void kernel_launch(void* const* d_in, const int* in_sizes, int n_in,
                              void* d_out, int out_size)
{
    const float* x   = (const float*)d_in[0];
    const int*   adj = (const int*)d_in[1];
    const float* W   = (const float*)d_in[2];
    const float* a   = (const float*)d_in[3];
    float*       out = (float*)d_out;

    static int smem_set = 0;
    if (!smem_set) {
        cudaFuncSetAttribute(k_attn, cudaFuncAttributeMaxDynamicSharedMemorySize, SM_TOT);
        smem_set = 1;
    }

    k_hgemm<<<dim3(MM/32, BB), 256>>>(x, W, a);
    k_attn<<<dim3(MM/MT, BB), 256, SM_TOT>>>(adj, out);
}

// round 7
// speedup vs baseline: 3.3221x; 1.3658x over previous
#include <cuda_runtime.h>
#include <cuda_bf16.h>
#include <math.h>
#include <stdint.h>

#define BB 8
#define MM 2048
#define FF 128
#define NT 32
#define NITER (MM/NT)   // 64
#define MT 64

// ---- scratch ----
__device__ __nv_bfloat16 g_ht_hi[BB*FF*MM];  // h^T hi  [b][f][n]
__device__ __nv_bfloat16 g_ht_lo[BB*FF*MM];  // h^T lo
__device__ float2 g_rpA[BB*MM];              // (e^{s1}, e^{0.2 s1})
__device__ float2 g_rpB[BB*MM];              // (e^{s2}, e^{0.2 s2})

__device__ __forceinline__ void cp_async16(uint32_t dst, const void* src) {
    asm volatile("cp.async.cg.shared.global [%0], [%1], 16;" :: "r"(dst), "l"(src));
}

#define LDSM4(r, addr) \
    asm volatile("ldmatrix.sync.aligned.m8n8.x4.shared.b16 {%0,%1,%2,%3}, [%4];" \
        : "=r"((r)[0]), "=r"((r)[1]), "=r"((r)[2]), "=r"((r)[3]) : "r"(addr))

#define MMA16816(c, a, b0, b1) \
    asm volatile("mma.sync.aligned.m16n8k16.row.col.f32.bf16.bf16.f32 " \
        "{%0,%1,%2,%3}, {%4,%5,%6,%7}, {%8,%9}, {%0,%1,%2,%3};" \
        : "+f"((c)[0]), "+f"((c)[1]), "+f"((c)[2]), "+f"((c)[3]) \
        : "r"((a)[0]), "r"((a)[1]), "r"((a)[2]), "r"((a)[3]), "r"(b0), "r"(b1))

__device__ __forceinline__ uint32_t pack_bf16x2(float hi, float lo) {
    uint32_t u;
    asm("cvt.rn.bf16x2.f32 %0, %1, %2;" : "=r"(u) : "f"(hi), "f"(lo));
    return u;
}

// SMEM layout (dynamic):
//  [0, 20480)       w tiles: buf*10240 + comp*5120; 64 rows x 80B
//  [20480, 61440)   h tiles: buf*20480 + comp*10240; 128 rows x 80B
//  [61440, 61696)   den_s (64 f32)
//  [61696, 62208)   c12 (64 float2)
#define SM_W     0
#define SM_H     20480
#define SM_DEN   61440
#define SM_C12   61696
#define SM_TOT   62208
#define W_COMP   5120
#define W_BUF    10240
#define H_COMP   10240
#define H_BUF    20480

// ---------------------------------------------------------------------------
// K1: h = x@W; writes h^T (bf16 hi/lo) + per-row exp coefficients.
// grid (64, 8), block 256. CTA = 32 rows.
// ---------------------------------------------------------------------------
__global__ __launch_bounds__(256) void k_hgemm(const float* __restrict__ x,
                                               const float* __restrict__ W,
                                               const float* __restrict__ a)
{
    __shared__ float Ws[8192];      // [64][128] GEMM stage; reused [32][130]
    __shared__ float xs[32][68];

    const int b   = blockIdx.y;
    const int m0  = blockIdx.x * 32;
    const int tid = threadIdx.x;
    const int row = tid >> 3;
    const int cg  = tid & 7;

    float acc[16];
#pragma unroll
    for (int j = 0; j < 16; j++) acc[j] = 0.f;

    const float* xb = x + ((size_t)b*MM + m0) * FF;

    for (int ch = 0; ch < 2; ch++) {
        const float4* Wv  = (const float4*)(W + ch*64*FF);
        float4*       Wsv = (float4*)Ws;
#pragma unroll
        for (int i = 0; i < 8; i++) Wsv[tid + i*256] = Wv[tid + i*256];
#pragma unroll
        for (int i = 0; i < 2; i++) {
            int idx = tid + i*256;
            int r = idx >> 4, q = (idx & 15) * 4;
            float4 v = *(const float4*)(xb + (size_t)r*FF + ch*64 + q);
            xs[r][q] = v.x; xs[r][q+1] = v.y; xs[r][q+2] = v.z; xs[r][q+3] = v.w;
        }
        __syncthreads();
#pragma unroll 8
        for (int i = 0; i < 64; i++) {
            float xv = xs[row][i];
#pragma unroll
            for (int t = 0; t < 4; t++)
#pragma unroll
                for (int j = 0; j < 4; j++)
                    acc[t*4+j] = fmaf(xv, Ws[i*128 + cg*4 + t*32 + j], acc[t*4+j]);
        }
        __syncthreads();
    }

    float p1 = 0.f, p2 = 0.f;
#pragma unroll
    for (int t = 0; t < 4; t++)
#pragma unroll
        for (int j = 0; j < 4; j++) {
            int col = cg*4 + t*32 + j;
            p1 = fmaf(acc[t*4+j], a[col],      p1);
            p2 = fmaf(acc[t*4+j], a[128+col],  p2);
        }
#pragma unroll
    for (int o = 4; o > 0; o >>= 1) {
        p1 += __shfl_down_sync(0xffffffffu, p1, o, 8);
        p2 += __shfl_down_sync(0xffffffffu, p2, o, 8);
    }
    if (cg == 0) {
        g_rpA[(size_t)b*MM + m0 + row] = make_float2(expf(p1), expf(0.2f*p1));
        g_rpB[(size_t)b*MM + m0 + row] = make_float2(expf(p2), expf(0.2f*p2));
    }

#pragma unroll
    for (int t = 0; t < 4; t++)
#pragma unroll
        for (int j = 0; j < 4; j++)
            Ws[row*130 + cg*4 + t*32 + j] = acc[t*4+j];
    __syncthreads();

    const int q  = tid & 7;
    const int fr = tid >> 3;
#pragma unroll
    for (int pass = 0; pass < 4; pass++) {
        int f = fr + 32*pass;
        float v0 = Ws[(q*4+0)*130 + f];
        float v1 = Ws[(q*4+1)*130 + f];
        float v2 = Ws[(q*4+2)*130 + f];
        float v3 = Ws[(q*4+3)*130 + f];
        __nv_bfloat16 h0 = __float2bfloat16_rn(v0);
        __nv_bfloat16 h1 = __float2bfloat16_rn(v1);
        __nv_bfloat16 h2 = __float2bfloat16_rn(v2);
        __nv_bfloat16 h3 = __float2bfloat16_rn(v3);
        uint32_t uh0 = (uint32_t)__bfloat16_as_ushort(h0) | ((uint32_t)__bfloat16_as_ushort(h1) << 16);
        uint32_t uh1 = (uint32_t)__bfloat16_as_ushort(h2) | ((uint32_t)__bfloat16_as_ushort(h3) << 16);
        uint32_t ul0 = pack_bf16x2(v1 - __bfloat162float(h1), v0 - __bfloat162float(h0));
        uint32_t ul1 = pack_bf16x2(v3 - __bfloat162float(h3), v2 - __bfloat162float(h2));
        size_t off = ((size_t)b*FF + f)*MM + m0 + q*4;
        *(uint2*)((char*)g_ht_hi + off*2) = make_uint2(uh0, uh1);
        *(uint2*)((char*)g_ht_lo + off*2) = make_uint2(ul0, ul1);
    }
}

// ---------------------------------------------------------------------------
// stage one h tile (hi+lo): 128 f rows x 64B, 1024 x 16B chunks.
// ---------------------------------------------------------------------------
__device__ __forceinline__ void stage_h(uint32_t hbase, int b, int n0, int tid)
{
#pragma unroll
    for (int e = 0; e < 4; e++) {
        int id    = tid + 256*e;
        int comp  = id >> 9;
        int f     = (id >> 2) & 127;
        int chunk = id & 3;
        const char* base = comp ? (const char*)g_ht_lo : (const char*)g_ht_hi;
        const char* src  = base + (((size_t)b*FF + f)*MM + n0 + chunk*8) * 2;
        cp_async16(hbase + comp*H_COMP + f*80 + chunk*16, src);
    }
    asm volatile("cp.async.commit_group;");
}

// ---------------------------------------------------------------------------
// K2: fused masked attention via mma.sync bf16 (3-term compensated).
// grid (32, 8), block 256 (8 warps), 2 CTAs/SM. CTA = 64 m-rows, full n sweep.
// Warp tile: wm = wid&3 -> m rows wm*16..+16; wf = wid>>2 -> f cols wf*64..+64.
// ---------------------------------------------------------------------------
__global__ __launch_bounds__(256, 2) void k_attn(const int* __restrict__ adj,
                                                 float* __restrict__ out)
{
    extern __shared__ char sm[];
    const uint32_t sbase = (uint32_t)__cvta_generic_to_shared(sm);
    float*  den_s = (float*)(sm + SM_DEN);
    float2* c12   = (float2*)(sm + SM_C12);

    const int b    = blockIdx.y;
    const int m0   = blockIdx.x * MT;
    const int tid  = threadIdx.x;
    const int wid  = tid >> 5;
    const int lane = tid & 31;
    const int c    = tid & 7;     // phase-A n quad
    const int r    = tid >> 3;    // phase-A row base (0..31); rows {r, r+32}

    if (tid < 64) c12[tid] = g_rpA[(size_t)b*MM + m0 + tid];

    const int* adjp = adj + ((size_t)(b*MM + m0 + r))*MM + c*4;
    int4 adjv[2];
#pragma unroll
    for (int i = 0; i < 2; i++)
        adjv[i] = __ldg((const int4*)(adjp + (size_t)32*i*MM));

    stage_h(sbase + SM_H, b, 0, tid);
    __syncthreads();

    float2 cc[2];
#pragma unroll
    for (int i = 0; i < 2; i++) cc[i] = c12[r + 32*i];
    float denp[2] = {0.f, 0.f};

    const int wm = wid & 3;
    const int wf = wid >> 2;
    const uint32_t offA = (uint32_t)((wm*16 + (lane & 7) + ((lane >> 3) & 1)*8)*80
                                     + (lane >> 4)*16);
    const uint32_t offB = (uint32_t)((wf*64 + (lane & 7) + ((lane >= 16) ? 8 : 0))*80
                                     + ((lane >> 3) & 1)*16);

    float C[8][4];
#pragma unroll
    for (int ft = 0; ft < 8; ft++)
#pragma unroll
        for (int j = 0; j < 4; j++) C[ft][j] = 0.f;

    for (int t = 0; t < NITER; t++) {
        const int buf = t & 1;
        const uint32_t wbase = sbase + SM_W + buf*W_BUF;
        const uint32_t hbase = sbase + SM_H + buf*H_BUF;

        // ---- build w tile (bf16 hi/lo) + exact fp32 den ----
        {
            const float4* rb = (const float4*)(g_rpB + (size_t)b*MM + t*NT) + c*2;
            float4 v0 = __ldg(rb), v1 = __ldg(rb + 1);
#pragma unroll
            for (int i = 0; i < 2; i++) {
                int4 av = adjv[i];
                int row = r + 32*i;
                float w0 = av.x ? fmaxf(cc[i].x*v0.x, cc[i].y*v0.y) : 0.f;
                float w1 = av.y ? fmaxf(cc[i].x*v0.z, cc[i].y*v0.w) : 0.f;
                float w2 = av.z ? fmaxf(cc[i].x*v1.x, cc[i].y*v1.y) : 0.f;
                float w3 = av.w ? fmaxf(cc[i].x*v1.z, cc[i].y*v1.w) : 0.f;
                denp[i] += (w0 + w1) + (w2 + w3);
                __nv_bfloat16 h0 = __float2bfloat16_rn(w0);
                __nv_bfloat16 h1 = __float2bfloat16_rn(w1);
                __nv_bfloat16 h2 = __float2bfloat16_rn(w2);
                __nv_bfloat16 h3 = __float2bfloat16_rn(w3);
                uint32_t uh0 = (uint32_t)__bfloat16_as_ushort(h0) | ((uint32_t)__bfloat16_as_ushort(h1) << 16);
                uint32_t uh1 = (uint32_t)__bfloat16_as_ushort(h2) | ((uint32_t)__bfloat16_as_ushort(h3) << 16);
                uint32_t ul0 = pack_bf16x2(w1 - __bfloat162float(h1), w0 - __bfloat162float(h0));
                uint32_t ul1 = pack_bf16x2(w3 - __bfloat162float(h3), w2 - __bfloat162float(h2));
                uint32_t o = wbase + row*80 + c*8;
                asm volatile("st.shared.v2.b32 [%0], {%1,%2};" :: "r"(o), "r"(uh0), "r"(uh1));
                asm volatile("st.shared.v2.b32 [%0], {%1,%2};" :: "r"(o + W_COMP), "r"(ul0), "r"(ul1));
            }
        }

        // adj prefetch for next tile
        {
            const int tn = (t+1 < NITER) ? (t+1)*NT : 0;
#pragma unroll
            for (int i = 0; i < 2; i++)
                adjv[i] = __ldg((const int4*)(adjp + (size_t)32*i*MM + tn));
        }

        asm volatile("cp.async.wait_group 0;");
        __syncthreads();

        if (t+1 < NITER)
            stage_h(sbase + SM_H + (buf^1)*H_BUF, b, (t+1)*NT, tid);

        // ---- mma: 2 k16-steps x 4 f-pairs x 3 passes ----
#pragma unroll
        for (int ks = 0; ks < 2; ks++) {
            uint32_t Ah[4], Al[4];
            LDSM4(Ah, wbase + offA + ks*32);
            LDSM4(Al, wbase + offA + ks*32 + W_COMP);
#pragma unroll
            for (int fp = 0; fp < 4; fp++) {
                uint32_t baddr = hbase + offB + fp*(16*80) + ks*32;
                uint32_t Bh[4], Bl[4];
                LDSM4(Bh, baddr);
                LDSM4(Bl, baddr + H_COMP);
                MMA16816(C[2*fp],   Ah, Bh[0], Bh[1]);
                MMA16816(C[2*fp],   Ah, Bl[0], Bl[1]);
                MMA16816(C[2*fp],   Al, Bh[0], Bh[1]);
                MMA16816(C[2*fp+1], Ah, Bh[2], Bh[3]);
                MMA16816(C[2*fp+1], Ah, Bl[2], Bl[3]);
                MMA16816(C[2*fp+1], Al, Bh[2], Bh[3]);
            }
        }
    }

    // den reduce over the 8 c-lanes sharing each row
#pragma unroll
    for (int i = 0; i < 2; i++)
#pragma unroll
        for (int o = 4; o > 0; o >>= 1)
            denp[i] += __shfl_down_sync(0xffffffffu, denp[i], o, 8);
    if (c == 0) {
#pragma unroll
        for (int i = 0; i < 2; i++) den_s[r + 32*i] = denp[i];
    }
    __syncthreads();

    // epilogue: normalize + ELU + store from fragments
    const int R0 = wm*16 + (lane >> 2);
    const float inv0 = 1.0f / den_s[R0];
    const float inv1 = 1.0f / den_s[R0 + 8];
    float* ob = out + ((size_t)b*MM + m0) * FF;
#pragma unroll
    for (int ft = 0; ft < 8; ft++) {
        int f0 = wf*64 + ft*8 + 2*(lane & 3);
        float e0 = C[ft][0] * inv0;
        float e1 = C[ft][1] * inv0;
        float e2 = C[ft][2] * inv1;
        float e3 = C[ft][3] * inv1;
        e0 = e0 > 0.f ? e0 : expm1f(e0);
        e1 = e1 > 0.f ? e1 : expm1f(e1);
        e2 = e2 > 0.f ? e2 : expm1f(e2);
        e3 = e3 > 0.f ? e3 : expm1f(e3);
        *(float2*)(ob + (size_t)R0*FF + f0)     = make_float2(e0, e1);
        *(float2*)(ob + (size_t)(R0+8)*FF + f0) = make_float2(e2, e3);
    }
}

extern "C" void kernel_launch(void* const* d_in, const int* in_sizes, int n_in,
                              void* d_out, int out_size)
{
    const float* x   = (const float*)d_in[0];
    const int*   adj = (const int*)d_in[1];
    const float* W   = (const float*)d_in[2];
    const float* a   = (const float*)d_in[3];
    float*       out = (float*)d_out;

    static int smem_set = 0;
    if (!smem_set) {
        cudaFuncSetAttribute(k_attn, cudaFuncAttributeMaxDynamicSharedMemorySize, SM_TOT);
        smem_set = 1;
    }

    k_hgemm<<<dim3(MM/32, BB), 256>>>(x, W, a);
    k_attn<<<dim3(MM/MT, BB), 256, SM_TOT>>>(adj, out);
}